// round 7
// baseline (speedup 1.0000x reference)
#include <cuda_runtime.h>
#include <math_constants.h>
#include <stdint.h>

#define KTOP 6              // K+1 with K=5
#define TPB  256
#define NSLOT 4             // mbarrier/smem ring depth
#define CHUNK_FLOATS 2048   // 8KB per chunk
#define CHUNK_BYTES  8192
#define CAP  1536           // candidate buffer (expected ~68 used)
#define THR  3.0f
#define EGATE 20.0855369f   // exp(THR): conservative gate on 4-elem exp sums

__device__ float g_row_loss[8192];
__device__ unsigned int g_ticket = 0;

__device__ __forceinline__ uint32_t smem_u32(const void* p) {
    return (uint32_t)__cvta_generic_to_shared(p);
}
__device__ __forceinline__ void mbar_init(uint32_t a, uint32_t cnt) {
    asm volatile("mbarrier.init.shared.b64 [%0], %1;" :: "r"(a), "r"(cnt) : "memory");
}
__device__ __forceinline__ void mbar_expect_tx(uint32_t a, uint32_t bytes) {
    asm volatile("mbarrier.arrive.expect_tx.shared.b64 _, [%0], %1;"
                 :: "r"(a), "r"(bytes) : "memory");
}
__device__ __forceinline__ void mbar_wait(uint32_t a, uint32_t parity) {
    asm volatile(
        "{\n\t.reg .pred P;\n"
        "W%=:\n\t"
        "mbarrier.try_wait.parity.acquire.cta.shared::cta.b64 P, [%0], %1, 0x989680;\n\t"
        "@P bra D%=;\n\t"
        "bra W%=;\n"
        "D%=:\n\t}"
        :: "r"(a), "r"(parity) : "memory");
}
__device__ __forceinline__ void bulk_g2s(uint32_t dst, const void* src,
                                         uint32_t bytes, uint32_t mbar) {
    asm volatile(
        "cp.async.bulk.shared::cta.global.mbarrier::complete_tx::bytes "
        "[%0], [%1], %2, [%3];"
        :: "r"(dst), "l"(src), "r"(bytes), "r"(mbar) : "memory");
}

__device__ __forceinline__ void topk_insert(float (&t)[KTOP], float v) {
    float x = v;
    #pragma unroll
    for (int j = 0; j < KTOP; ++j) {
        float hi = fmaxf(t[j], x);
        float lo = fminf(t[j], x);
        t[j] = hi; x = lo;
    }
}
__device__ __forceinline__ void push_cand(float v, int idx, int yi,
                                          int* scnt, float* cval) {
    if (v > THR && idx != yi) {
        int pos = atomicAdd(scnt, 1);
        if (pos < CAP) cval[pos] = v;
    }
}
// exp-sum one float4; candidate gate derived from the partial sum (free:
// exps >= 0 and exp monotone => elem > THR forces q >= exp(THR)).
__device__ __forceinline__ void proc_vec(float4 a, int base, int yi,
                                         float& s, int* scnt, float* cval) {
    float e0 = __expf(a.x), e1 = __expf(a.y), e2 = __expf(a.z), e3 = __expf(a.w);
    float q = (e0 + e1) + (e2 + e3);
    s += q;
    if (q > EGATE) {
        push_cand(a.x, base + 0, yi, scnt, cval);
        push_cand(a.y, base + 1, yi, scnt, cval);
        push_cand(a.z, base + 2, yi, scnt, cval);
        push_cand(a.w, base + 3, yi, scnt, cval);
    }
}

__global__ __launch_bounds__(TPB) void autkc_fused_kernel(
    const float* __restrict__ pred,
    const int*   __restrict__ ylab,
    int C, int B,
    float* __restrict__ out)
{
    const int row = blockIdx.x;
    const float* __restrict__ p = pred + (long long)row * (long long)C;
    const int yi  = ylab[row];
    const int tid = threadIdx.x;

    __shared__ alignas(16) float sbuf[NSLOT][CHUNK_FLOATS];   // 32 KB
    __shared__ alignas(8) unsigned long long mbar_sto[NSLOT];
    __shared__ float cval[CAP];
    __shared__ int   scnt;
    __shared__ float shsum[TPB / 32];
    __shared__ float wval[TPB / 32];
    __shared__ int   widx[TPB / 32];
    __shared__ float topv[KTOP];
    __shared__ int   is_last;

    const uint32_t mb0   = smem_u32(&mbar_sto[0]);
    const uint32_t sbuf0 = smem_u32(&sbuf[0][0]);

    if (tid == 0) {
        scnt = 0;
        #pragma unroll
        for (int s = 0; s < NSLOT; ++s) mbar_init(mb0 + 8u * s, 1);
    }
    __syncthreads();

    float s0 = 0.f, s1 = 0.f;

    // ---- peel to 16B alignment (row base only 4B aligned; C odd) ----
    const int mis  = (int)(((uintptr_t)p & 15u) >> 2);
    const int peel = ((4 - mis) & 3);
    for (int i = tid; i < peel && i < C; i += TPB) {
        float v = p[i];
        s0 += __expf(v);
        push_cand(v, i, yi, &scnt, cval);
    }

    const float* pa = p + peel;              // 16B aligned
    const int remain = C - peel;
    const int nchunk = remain / CHUNK_FLOATS;

    // ---- TMA-bulk prologue: prefetch up to 3 chunks ----
    if (tid == 0) {
        #pragma unroll
        for (int c = 0; c < NSLOT - 1; ++c) {
            if (c < nchunk) {
                mbar_expect_tx(mb0 + 8u * c, CHUNK_BYTES);
                bulk_g2s(sbuf0 + (uint32_t)c * CHUNK_BYTES,
                         pa + (long long)c * CHUNK_FLOATS, CHUNK_BYTES,
                         mb0 + 8u * c);
            }
        }
    }

    // ---- mainloop: wait chunk c, refill chunk c+3, consume ----
    for (int c = 0; c < nchunk; ++c) {
        const int      slot   = c & (NSLOT - 1);
        const uint32_t parity = (uint32_t)((c >> 2) & 1);
        mbar_wait(mb0 + 8u * slot, parity);

        if (tid == 0) {
            int nf = c + NSLOT - 1;
            if (nf < nchunk) {
                int ns = nf & (NSLOT - 1);       // == (c-1)&3: consumed + fenced
                mbar_expect_tx(mb0 + 8u * ns, CHUNK_BYTES);
                bulk_g2s(sbuf0 + (uint32_t)ns * CHUNK_BYTES,
                         pa + (long long)nf * CHUNK_FLOATS, CHUNK_BYTES,
                         mb0 + 8u * ns);
            }
        }

        const float4* sv = (const float4*)&sbuf[slot][0];
        float4 a = sv[tid];
        float4 b = sv[tid + TPB];
        const int gbase = peel + c * CHUNK_FLOATS;
        proc_vec(a, gbase + 4 * tid,         yi, s0, &scnt, cval);
        proc_vec(b, gbase + 4 * (tid + TPB), yi, s1, &scnt, cval);
        __syncthreads();      // all reads of this slot done before its reuse
    }

    // ---- tails: vector then scalar, straight from global ----
    const int tstart = peel + nchunk * CHUNK_FLOATS;
    const int tvec   = (C - tstart) >> 2;
    const float4* pt = (const float4*)(p + tstart);     // 16B aligned
    for (int j = tid; j < tvec; j += TPB) {
        float4 a = __ldcs(&pt[j]);
        proc_vec(a, tstart + 4 * j, yi, s0, &scnt, cval);
    }
    for (int i = tstart + 4 * tvec + tid; i < C; i += TPB) {
        float v = p[i];
        s0 += __expf(v);
        push_cand(v, i, yi, &scnt, cval);
    }

    float s = s0 + s1;
    #pragma unroll
    for (int o = 16; o > 0; o >>= 1) s += __shfl_down_sync(0xffffffffu, s, o);
    if ((tid & 31) == 0) shsum[tid >> 5] = s;
    __syncthreads();

    // ---- candidate count check; exact fallback for adversarial input ----
    int n = scnt;
    if (n < KTOP || n > CAP) {
        float t[KTOP];
        #pragma unroll
        for (int k = 0; k < KTOP; ++k) t[k] = -CUDART_INF_F;
        float thr2 = -CUDART_INF_F;
        for (int i = tid; i < C; i += TPB) {
            float v = p[i];
            if (v > thr2 && i != yi) { topk_insert(t, v); thr2 = t[KTOP - 1]; }
        }
        __syncthreads();
        #pragma unroll
        for (int k = 0; k < KTOP; ++k) cval[tid + k * TPB] = t[k];
        n = TPB * KTOP;
        __syncthreads();
    }

    // ---- top-6 of cval[0..n): 6 masked argmax rounds ----
    for (int r = 0; r < KTOP; ++r) {
        float bv = -CUDART_INF_F;
        int   bi = 0;
        for (int i = tid; i < n; i += TPB) {
            float v = cval[i];
            if (v > bv) { bv = v; bi = i; }
        }
        #pragma unroll
        for (int o = 16; o > 0; o >>= 1) {
            float ov = __shfl_down_sync(0xffffffffu, bv, o);
            int   oi = __shfl_down_sync(0xffffffffu, bi, o);
            if (ov > bv) { bv = ov; bi = oi; }
        }
        if ((tid & 31) == 0) { wval[tid >> 5] = bv; widx[tid >> 5] = bi; }
        __syncthreads();
        if (tid == 0) {
            float best = -CUDART_INF_F;
            int   besti = 0;
            #pragma unroll
            for (int w = 0; w < TPB / 32; ++w)
                if (wval[w] > best) { best = wval[w]; besti = widx[w]; }
            topv[r] = best;
            cval[besti] = -CUDART_INF_F;
        }
        __syncthreads();
    }

    // ---- per-row loss + fused last-CTA mean ----
    if (tid == 0) {
        float S_total = 0.0f;
        #pragma unroll
        for (int w = 0; w < TPB / 32; ++w) S_total += shsum[w];
        float invS = 1.0f / S_total;
        float py   = __expf(p[yi]) * invS;
        float acc  = 0.0f;
        #pragma unroll
        for (int r = 0; r < KTOP; ++r) {
            float pi = __expf(topv[r]) * invS;
            float dd = 1.0f + pi - py;
            acc += dd * dd;
        }
        g_row_loss[row] = acc * (1.0f / (float)(KTOP - 1));   // /K
        __threadfence();
        unsigned int done = atomicAdd(&g_ticket, 1u);
        is_last = (done == (unsigned int)(B - 1)) ? 1 : 0;
    }
    __syncthreads();

    if (is_last) {
        __threadfence();
        float fs = 0.0f;
        for (int i = tid; i < B; i += TPB) fs += g_row_loss[i];
        #pragma unroll
        for (int o = 16; o > 0; o >>= 1) fs += __shfl_down_sync(0xffffffffu, fs, o);
        if ((tid & 31) == 0) shsum[tid >> 5] = fs;
        __syncthreads();
        if (tid == 0) {
            float tot = 0.0f;
            #pragma unroll
            for (int w = 0; w < TPB / 32; ++w) tot += shsum[w];
            out[0] = tot / (float)B;
            g_ticket = 0;   // reset for next graph replay
        }
    }
}

extern "C" void kernel_launch(void* const* d_in, const int* in_sizes, int n_in,
                              void* d_out, int out_size)
{
    const float* pred = (const float*)d_in[0];
    const int*   y    = (const int*)d_in[1];
    // d_in[2] = epoch, unused (AUTKC branch taken for epoch >= 0)

    const int B = in_sizes[1];
    const int C = in_sizes[0] / B;

    autkc_fused_kernel<<<B, TPB>>>(pred, y, C, B, (float*)d_out);
}

// round 8
// speedup vs baseline: 1.0508x; 1.0508x over previous
#include <cuda_runtime.h>
#include <math_constants.h>
#include <stdint.h>

#define KTOP 6       // K+1 with K=5
#define TPB  128
#define CAP  1536    // candidate buffer capacity (expected ~68 used)
#define THR  3.0f    // candidate threshold; guarded by exact fallback
#define EGATE 20.0855369f   // exp(THR): conservative gate on 4-elem exp sums

__device__ float g_row_loss[8192];
__device__ unsigned int g_ticket = 0;

__device__ __forceinline__ void topk_insert(float (&t)[KTOP], float v) {
    float x = v;
    #pragma unroll
    for (int j = 0; j < KTOP; ++j) {
        float hi = fmaxf(t[j], x);
        float lo = fminf(t[j], x);
        t[j] = hi; x = lo;
    }
}

__device__ __forceinline__ void push_cand(float v, int idx, int yi,
                                          int* scnt, float* cval) {
    if (v > THR && idx != yi) {
        int pos = atomicAdd(scnt, 1);
        if (pos < CAP) cval[pos] = v;
    }
}

// exp-sum one float4 into s; candidate gate derived from the partial sum.
// exps >= 0 and exp monotone => any elem > THR forces q >= exp(THR), so the
// gate is conservative (never misses); false positives just re-test exactly.
__device__ __forceinline__ void proc_vec(float4 a, int base, int yi,
                                         float& s, int* scnt, float* cval) {
    float e0 = __expf(a.x), e1 = __expf(a.y), e2 = __expf(a.z), e3 = __expf(a.w);
    float q = (e0 + e1) + (e2 + e3);
    s += q;
    if (q > EGATE) {                      // rare (~1% of thread-vectors)
        push_cand(a.x, base + 0, yi, scnt, cval);
        push_cand(a.y, base + 1, yi, scnt, cval);
        push_cand(a.z, base + 2, yi, scnt, cval);
        push_cand(a.w, base + 3, yi, scnt, cval);
    }
}

__global__ __launch_bounds__(TPB) void autkc_fused_kernel(
    const float* __restrict__ pred,
    const int*   __restrict__ ylab,
    int C, int B,
    float* __restrict__ out)
{
    const int row = blockIdx.x;
    const float* __restrict__ p = pred + (long long)row * (long long)C;
    const int yi  = ylab[row];
    const int tid = threadIdx.x;

    __shared__ float cval[CAP];
    __shared__ int   scnt;
    __shared__ float shsum[TPB / 32];
    __shared__ float wval[TPB / 32];
    __shared__ int   widx[TPB / 32];
    __shared__ float topv[KTOP];
    __shared__ int   is_last;

    if (tid == 0) scnt = 0;
    __syncthreads();

    float s0 = 0.f, s1 = 0.f, s2 = 0.f, s3 = 0.f;

    // ---- alignment peel (row base may not be 16B aligned; C odd) ----
    const int mis  = (int)(((uintptr_t)p & 15u) >> 2);
    const int peel = ((4 - mis) & 3);
    for (int i = tid; i < peel && i < C; i += TPB) {
        float v = p[i];
        s0 += __expf(v);
        push_cand(v, i, yi, &scnt, cval);
    }

    const int nvec = (C - peel) >> 2;
    const float4* __restrict__ pv = (const float4*)(p + peel);

    // ---- hot streaming loop: 4 front-batched LDG.128 per iteration ----
    int j = tid;
    for (; j + 3 * TPB < nvec; j += 4 * TPB) {
        float4 a = __ldcs(&pv[j]);
        float4 b = __ldcs(&pv[j +     TPB]);
        float4 c = __ldcs(&pv[j + 2 * TPB]);
        float4 d = __ldcs(&pv[j + 3 * TPB]);
        int ba = peel + 4 * j;
        proc_vec(a, ba,            yi, s0, &scnt, cval);
        proc_vec(b, ba + 4 * TPB,  yi, s1, &scnt, cval);
        proc_vec(c, ba + 8 * TPB,  yi, s2, &scnt, cval);
        proc_vec(d, ba + 12 * TPB, yi, s3, &scnt, cval);
    }
    for (; j < nvec; j += TPB) {
        float4 a = __ldcs(&pv[j]);
        proc_vec(a, peel + 4 * j, yi, s0, &scnt, cval);
    }
    for (int i = peel + 4 * nvec + tid; i < C; i += TPB) {
        float v = p[i];
        s0 += __expf(v);
        push_cand(v, i, yi, &scnt, cval);
    }

    float s = (s0 + s1) + (s2 + s3);
    #pragma unroll
    for (int o = 16; o > 0; o >>= 1) s += __shfl_down_sync(0xffffffffu, s, o);
    if ((tid & 31) == 0) shsum[tid >> 5] = s;
    __syncthreads();

    // ---- candidate count check; exact fallback for adversarial input ----
    int n = scnt;
    if (n < KTOP || n > CAP) {
        float t[KTOP];
        #pragma unroll
        for (int k = 0; k < KTOP; ++k) t[k] = -CUDART_INF_F;
        float thr2 = -CUDART_INF_F;
        for (int i = tid; i < C; i += TPB) {
            float v = p[i];
            if (v > thr2 && i != yi) { topk_insert(t, v); thr2 = t[KTOP - 1]; }
        }
        __syncthreads();
        #pragma unroll
        for (int k = 0; k < KTOP; ++k) cval[tid + k * TPB] = t[k];
        n = TPB * KTOP;
        __syncthreads();
    }

    // ---- top-6 of cval[0..n): 6 masked argmax rounds ----
    for (int r = 0; r < KTOP; ++r) {
        float bv = -CUDART_INF_F;
        int   bi = 0;
        for (int i = tid; i < n; i += TPB) {
            float v = cval[i];
            if (v > bv) { bv = v; bi = i; }
        }
        #pragma unroll
        for (int o = 16; o > 0; o >>= 1) {
            float ov = __shfl_down_sync(0xffffffffu, bv, o);
            int   oi = __shfl_down_sync(0xffffffffu, bi, o);
            if (ov > bv) { bv = ov; bi = oi; }
        }
        if ((tid & 31) == 0) { wval[tid >> 5] = bv; widx[tid >> 5] = bi; }
        __syncthreads();
        if (tid == 0) {
            float best = -CUDART_INF_F;
            int   besti = 0;
            #pragma unroll
            for (int w = 0; w < TPB / 32; ++w)
                if (wval[w] > best) { best = wval[w]; besti = widx[w]; }
            topv[r] = best;
            cval[besti] = -CUDART_INF_F;
        }
        __syncthreads();
    }

    // ---- per-row loss + fused last-CTA mean ----
    if (tid == 0) {
        float S_total = 0.0f;
        #pragma unroll
        for (int w = 0; w < TPB / 32; ++w) S_total += shsum[w];
        float invS = 1.0f / S_total;
        float py   = __expf(p[yi]) * invS;
        float acc  = 0.0f;
        #pragma unroll
        for (int r = 0; r < KTOP; ++r) {
            float pi = __expf(topv[r]) * invS;
            float dd = 1.0f + pi - py;
            acc += dd * dd;
        }
        g_row_loss[row] = acc * (1.0f / (float)(KTOP - 1));   // /K
        __threadfence();
        unsigned int done = atomicAdd(&g_ticket, 1u);
        is_last = (done == (unsigned int)(B - 1)) ? 1 : 0;
    }
    __syncthreads();

    if (is_last) {
        __threadfence();
        float fs = 0.0f;
        for (int i = tid; i < B; i += TPB) fs += g_row_loss[i];
        #pragma unroll
        for (int o = 16; o > 0; o >>= 1) fs += __shfl_down_sync(0xffffffffu, fs, o);
        if ((tid & 31) == 0) shsum[tid >> 5] = fs;
        __syncthreads();
        if (tid == 0) {
            float tot = 0.0f;
            #pragma unroll
            for (int w = 0; w < TPB / 32; ++w) tot += shsum[w];
            out[0] = tot / (float)B;
            g_ticket = 0;   // reset for next graph replay
        }
    }
}

extern "C" void kernel_launch(void* const* d_in, const int* in_sizes, int n_in,
                              void* d_out, int out_size)
{
    const float* pred = (const float*)d_in[0];
    const int*   y    = (const int*)d_in[1];
    // d_in[2] = epoch, unused (AUTKC branch taken for epoch >= 0)

    const int B = in_sizes[1];
    const int C = in_sizes[0] / B;

    autkc_fused_kernel<<<B, TPB>>>(pred, y, C, B, (float*)d_out);
}